// round 2
// baseline (speedup 1.0000x reference)
#include <cuda_runtime.h>
#include <math.h>

#define NB   4
#define NPT  4096
#define NS   4096
#define CIND 128
#define DIMD 64
#define KNNK 20
#define MTOT (NB*NPT*KNNK)   /* 327680 */
#define PTOT (NB*NPT)        /* 16384  */

// ---------------- static device scratch (no runtime allocation) ----------------
__device__ float g_q[PTOT*DIMD];
__device__ float g_k[PTOT*DIMD];
__device__ float g_v[PTOT*DIMD];
__device__ int   g_idx[PTOT*KNNK];
__device__ float g_h [MTOT*DIMD];     // [m][d]
__device__ float g_vg[MTOT*DIMD];     // [m][d]
__device__ float g_a [MTOT*256];      // [m][c]
__device__ float g_logits[MTOT*128];  // [m][r*64+o]
__device__ float g_agg[PTOT*2*DIMD];  // [q][d], q = point*2+r
__device__ float g_aw1t[64*256];      // [d][c]   transposed aw1
__device__ float g_w2t[256*128];      // [c][r*64+o]  permuted awt
__device__ float g_wet[64*128];       // [d][o2]  transposed we
__device__ float g_abn[512];          // [0:256) inv, [256:512) fused bias

// ============================================================================
// Setup: transpose/permute weights, fold BN constants. One-shot, tiny.
// ============================================================================
__global__ void setup_kernel(const float* __restrict__ aw1, const float* __restrict__ awt,
                             const float* __restrict__ we,  const float* __restrict__ ag,
                             const float* __restrict__ av,  const float* __restrict__ ab1,
                             const float* __restrict__ am,  const float* __restrict__ abt2)
{
    int i0 = blockIdx.x*256 + threadIdx.x;
    int stride = gridDim.x*256;
    for (int i=i0; i<64*256; i+=stride) { int d=i>>8, c=i&255; g_aw1t[i] = aw1[c*64+d]; }
    for (int i=i0; i<256*128; i+=stride) {
        int c=i>>7, oo=i&127; int r=oo>>6, o=oo&63;
        g_w2t[i] = awt[c*128 + o*2 + r];
    }
    for (int i=i0; i<64*128; i+=stride) { int d=i>>7, o2=i&127; g_wet[i] = we[o2*64+d]; }
    for (int i=i0; i<256; i+=stride) {
        float inv = ag[i]*rsqrtf(av[i]+1e-5f);
        g_abn[i]     = inv;
        g_abn[256+i] = (ab1[i]-am[i])*inv + abt2[i];
    }
}

// ============================================================================
// Kernel 1: q/k/v 1x1 conv.  out[point][d] = W[d][:] . in[b][:][n] + bias[d]
// grid (256, B, 3), block 256.
// ============================================================================
__global__ __launch_bounds__(256) void qkv_kernel(
    const float* __restrict__ query, const float* __restrict__ key_feat,
    const float* __restrict__ wq, const float* __restrict__ bq,
    const float* __restrict__ wk, const float* __restrict__ bk,
    const float* __restrict__ wv, const float* __restrict__ bv)
{
    __shared__ float Wsm[64*129];
    __shared__ __align__(16) float xs[128*16];
    int t = threadIdx.x;
    int z = blockIdx.z;
    const float* W    = (z==0)? wq : (z==1)? wk : wv;
    const float* bias = (z==0)? bq : (z==1)? bk : bv;
    const float* inp  = (z==0)? query : key_feat;
    float* outp       = (z==0)? g_q : (z==1)? g_k : g_v;
    int b  = blockIdx.y;
    int n0 = blockIdx.x * 16;

    for (int idx=t; idx<64*128; idx+=256) Wsm[(idx>>7)*129 + (idx&127)] = W[idx];
    for (int idx=t; idx<128*16; idx+=256) {
        int c = idx>>4, i = idx&15;
        xs[c*16+i] = inp[(b*CIND+c)*NPT + n0 + i];
    }
    __syncthreads();

    int d = t & 63, g = t >> 6;
    float bb = bias[d];
    float acc0=bb, acc1=bb, acc2=bb, acc3=bb;
    for (int c=0; c<128; ++c) {
        float w = Wsm[d*129+c];
        float4 v4 = *(const float4*)&xs[c*16 + g*4];
        acc0 += w*v4.x; acc1 += w*v4.y; acc2 += w*v4.z; acc3 += w*v4.w;
    }
    int pb = (b*NPT + n0 + g*4);
    outp[(pb+0)*DIMD + d] = acc0;
    outp[(pb+1)*DIMD + d] = acc1;
    outp[(pb+2)*DIMD + d] = acc2;
    outp[(pb+3)*DIMD + d] = acc3;
}

// ============================================================================
// Kernel 2: KNN (top-20 smallest d = |p1|^2+|p2|^2-2 p1.p2, stable ties).
// grid (32, B), block 128 (one query per thread), pos2 tiled 2048/chunk.
// ============================================================================
__global__ __launch_bounds__(128) void knn_kernel(
    const float* __restrict__ pos1, const float* __restrict__ pos2)
{
    __shared__ float4 sp[2048];
    int t = threadIdx.x;
    int b = blockIdx.y;
    int n = blockIdx.x*128 + t;
    const float* p1 = pos1 + b*3*NPT;
    float qx = p1[n], qy = p1[NPT+n], qz = p1[2*NPT+n];
    float s1 = qx*qx + qy*qy + qz*qz;

    float bd[KNNK]; int bi[KNNK];
    #pragma unroll
    for (int i=0;i<KNNK;++i) { bd[i]=1e30f; bi[i]=0; }

    const float* p2 = pos2 + b*3*NS;
    for (int ch=0; ch<2; ++ch) {
        __syncthreads();
        for (int j=t; j<2048; j+=128) {
            int jg = ch*2048 + j;
            float x=p2[jg], y=p2[NS+jg], z=p2[2*NS+jg];
            sp[j] = make_float4(x, y, z, x*x+y*y+z*z);
        }
        __syncthreads();
        for (int j=0; j<2048; ++j) {
            float4 p = sp[j];
            float dd = s1 + p.w - 2.0f*(qx*p.x + qy*p.y + qz*p.z);
            if (dd < bd[KNNK-1]) {
                int jg = ch*2048 + j;
                #pragma unroll
                for (int i=KNNK-1; i>=1; --i) {
                    if (dd < bd[i]) {
                        bool sh = dd < bd[i-1];
                        bd[i] = sh ? bd[i-1] : dd;
                        bi[i] = sh ? bi[i-1] : jg;
                    }
                }
                if (dd < bd[0]) { bd[0]=dd; bi[0]=jg; }
            }
        }
    }
    int* op = &g_idx[(b*NPT + n)*KNNK];
    #pragma unroll
    for (int i=0;i<KNNK;++i) op[i] = bi[i];
}

// ============================================================================
// Kernel 3: gather + pos-MLP; h = q - k_g + pe ; vg = v_g + pe
// grid 8192 (2 points/CTA), block 128.
// ============================================================================
__global__ __launch_bounds__(128) void prep_kernel(
    const float* __restrict__ pos1, const float* __restrict__ pos2,
    const float* __restrict__ pw1, const float* __restrict__ pb1,
    const float* __restrict__ pg,  const float* __restrict__ pbt,
    const float* __restrict__ pm,  const float* __restrict__ pvv,
    const float* __restrict__ pw2, const float* __restrict__ pb2)
{
    __shared__ float pw2s[64*65];
    __shared__ __align__(16) float pe1s[2][64*24];
    __shared__ float prel[2][3][KNNK];
    __shared__ float qs[2][64];
    __shared__ int idxs[2][KNNK];
    int t = threadIdx.x;
    int p0 = blockIdx.x*2;

    for (int idx=t; idx<64*64; idx+=128) pw2s[(idx>>6)*65 + (idx&63)] = pw2[idx];
    if (t < 2*KNNK) idxs[t/KNNK][t%KNNK] = g_idx[p0*KNNK + t];
    {
        int pp = t>>6, d = t&63;
        qs[pp][d] = g_q[(p0+pp)*DIMD + d];
    }
    __syncthreads();

    if (t < 2*3*KNNK) {
        int pp = t/(3*KNNK), r = t%(3*KNNK);
        int c = r/KNNK, k = r%KNNK;
        int p = p0+pp, b = p>>12, n = p&4095;
        prel[pp][c][k] = pos1[(b*3+c)*NPT + n] - pos2[(b*3+c)*NS + idxs[pp][k]];
    }
    __syncthreads();

    {   // pe1 = relu(bn(pw1 @ pos_rel + pb1))
        int cH = t & 63, pp = t >> 6;
        float w0 = pw1[cH*3], w1 = pw1[cH*3+1], w2v = pw1[cH*3+2];
        float inv = pg[cH]*rsqrtf(pvv[cH]+1e-5f);
        float tb  = (pb1[cH]-pm[cH])*inv + pbt[cH];
        #pragma unroll
        for (int k=0;k<KNNK;++k) {
            float s = w0*prel[pp][0][k] + w1*prel[pp][1][k] + w2v*prel[pp][2][k];
            pe1s[pp][cH*24+k] = fmaxf(s*inv + tb, 0.0f);
        }
    }
    __syncthreads();

    {   // pe = pw2 @ pe1 + pb2 ; emit h, vg
        int d = t&63, pp = t>>6;
        int p = p0+pp, b = p>>12;
        float acc[KNNK]; float bias = pb2[d];
        #pragma unroll
        for (int k=0;k<KNNK;++k) acc[k]=bias;
        for (int cH=0;cH<64;++cH) {
            float w = pw2s[d*65+cH];
            #pragma unroll
            for (int k4=0;k4<5;++k4) {
                float4 v4 = *(const float4*)&pe1s[pp][cH*24 + k4*4];
                acc[k4*4+0]+=w*v4.x; acc[k4*4+1]+=w*v4.y;
                acc[k4*4+2]+=w*v4.z; acc[k4*4+3]+=w*v4.w;
            }
        }
        float qv = qs[pp][d];
        #pragma unroll
        for (int k=0;k<KNNK;++k) {
            int j = idxs[pp][k];
            int m = p*KNNK + k;
            float kg = g_k[(b*NS+j)*DIMD + d];
            float vv = g_v[(b*NS+j)*DIMD + d];
            g_h [m*DIMD + d] = qv - kg + acc[k];
            g_vg[m*DIMD + d] = vv + acc[k];
        }
    }
}

// ============================================================================
// Kernel 4: GEMM1  a[m][c] = relu(bn_fused(aw1t . h))   c in 256, K=64
// grid 5120 (64 m-rows/CTA), block 256. Thread: 8m x 8c register tile.
// Weights streamed via LDG (64KB, L1-resident); activations via smem bcast.
// ============================================================================
__global__ __launch_bounds__(256) void gemm1_kernel()
{
    __shared__ float hs[64*64];
    int t = threadIdx.x;
    int m0 = blockIdx.x*64;
    int cg = t & 31, mg = t >> 5;
    for (int idx=t; idx<64*64; idx+=256) hs[idx] = g_h[m0*64 + idx];
    __syncthreads();

    float acc[8][8];
    #pragma unroll
    for (int j=0;j<8;++j)
        #pragma unroll
        for (int i=0;i<8;++i) acc[j][i]=0.f;

    for (int d=0; d<64; ++d) {
        float hv[8];
        #pragma unroll
        for (int i=0;i<8;++i) hv[i] = hs[(mg*8+i)*64 + d];
        #pragma unroll
        for (int j=0;j<8;++j) {
            float w = __ldg(&g_aw1t[d*256 + cg + 32*j]);
            #pragma unroll
            for (int i=0;i<8;++i) acc[j][i] += w*hv[i];
        }
    }
    #pragma unroll
    for (int j=0;j<8;++j) {
        int c = cg + 32*j;
        float inv = g_abn[c], tb = g_abn[256+c];
        #pragma unroll
        for (int i=0;i<8;++i)
            g_a[(m0+mg*8+i)*256 + c] = fmaxf(acc[j][i]*inv + tb, 0.f);
    }
}

// ============================================================================
// Kernel 5: GEMM2  logits[m][o'] = W2[o'][:] . a[m][:]   o' in 128, K=256
// grid 5120, block 256. K chunked in 2 (smem <= 32KB). 8m x 4o' per thread.
// ============================================================================
__global__ __launch_bounds__(256) void gemm2_kernel()
{
    __shared__ float as_[64*128];
    int t = threadIdx.x;
    int m0 = blockIdx.x*64;
    int cg = t & 31, mg = t >> 5;

    float acc[4][8];
    #pragma unroll
    for (int j=0;j<4;++j)
        #pragma unroll
        for (int i=0;i<8;++i) acc[j][i]=0.f;

    for (int ch=0; ch<2; ++ch) {
        __syncthreads();
        for (int idx=t; idx<64*128; idx+=256) {
            int mi = idx>>7, cc = idx&127;
            as_[idx] = g_a[(m0+mi)*256 + ch*128 + cc];
        }
        __syncthreads();
        for (int cc=0; cc<128; ++cc) {
            float hv[8];
            #pragma unroll
            for (int i=0;i<8;++i) hv[i] = as_[(mg*8+i)*128 + cc];
            #pragma unroll
            for (int j=0;j<4;++j) {
                float w = __ldg(&g_w2t[(ch*128+cc)*128 + cg + 32*j]);
                #pragma unroll
                for (int i=0;i<8;++i) acc[j][i] += w*hv[i];
            }
        }
    }
    #pragma unroll
    for (int j=0;j<4;++j)
        #pragma unroll
        for (int i=0;i<8;++i)
            g_logits[(m0+mg*8+i)*128 + cg + 32*j] = acc[j][i];
}

// ============================================================================
// Kernel 6: softmax over k (=20) + weighted aggregation of vg.
// grid 8192 (2 points/CTA), block 256; thread = (point, r*64+d) channel.
// ============================================================================
__global__ __launch_bounds__(256) void softmax_kernel()
{
    int t = threadIdx.x;
    int p = blockIdx.x*2 + (t>>7);
    int chn = t & 127;          // r*64 + d
    int d = chn & 63;

    const float* lp = &g_logits[p*KNNK*128 + chn];
    float lg[KNNK];
    #pragma unroll
    for (int k=0;k<KNNK;++k) lg[k] = lp[k*128];
    float mx = lg[0];
    #pragma unroll
    for (int k=1;k<KNNK;++k) mx = fmaxf(mx, lg[k]);
    float s = 0.f;
    #pragma unroll
    for (int k=0;k<KNNK;++k) { lg[k] = __expf(lg[k]-mx); s += lg[k]; }
    float inv = 1.f/s;

    const float* vp = &g_vg[p*KNNK*64 + d];
    float acc = 0.f;
    #pragma unroll
    for (int k=0;k<KNNK;++k) acc += lg[k]*vp[k*64];
    g_agg[p*128 + chn] = acc*inv;
}

// ============================================================================
// Kernel 7: final 1x1 conv (DIM->CIN) + residual (nearest-upsampled query).
// grid 2048 (16 output positions/CTA), block 256.
// ============================================================================
__global__ __launch_bounds__(256) void final_kernel(
    const float* __restrict__ query, const float* __restrict__ be,
    float* __restrict__ out)
{
    __shared__ float wes[64*128];
    __shared__ __align__(16) float aggt[64*16];
    int t = threadIdx.x;
    int q0 = blockIdx.x*16;
    for (int idx=t; idx<64*128; idx+=256) wes[idx] = g_wet[idx];
    for (int idx=t; idx<16*64; idx+=256) {
        int li = idx>>6, d = idx&63;
        aggt[d*16+li] = g_agg[(q0+li)*64 + d];
    }
    __syncthreads();

    int o2 = t & 127, h = t >> 7;
    float acc[8];
    #pragma unroll
    for (int i=0;i<8;++i) acc[i]=0.f;
    for (int d=0; d<64; ++d) {
        float w = wes[d*128+o2];
        float4 a0 = *(const float4*)&aggt[d*16 + h*8];
        float4 a1 = *(const float4*)&aggt[d*16 + h*8 + 4];
        acc[0]+=w*a0.x; acc[1]+=w*a0.y; acc[2]+=w*a0.z; acc[3]+=w*a0.w;
        acc[4]+=w*a1.x; acc[5]+=w*a1.y; acc[6]+=w*a1.z; acc[7]+=w*a1.w;
    }
    float bb = be[o2];
    #pragma unroll
    for (int i=0;i<8;++i) {
        int qq = q0 + h*8 + i;
        int b = qq >> 13, nr = qq & 8191, n = nr >> 1;
        out[b*(128*8192) + o2*8192 + nr] = acc[i] + bb
            + query[b*(128*4096) + o2*4096 + n];
    }
}

// ============================================================================
extern "C" void kernel_launch(void* const* d_in, const int* in_sizes, int n_in,
                              void* d_out, int out_size)
{
    const float* pos1     = (const float*)d_in[0];
    const float* query    = (const float*)d_in[1];
    const float* pos2     = (const float*)d_in[2];
    const float* key_feat = (const float*)d_in[3];
    const float* wq  = (const float*)d_in[4];
    const float* bq  = (const float*)d_in[5];
    const float* wk  = (const float*)d_in[6];
    const float* bk  = (const float*)d_in[7];
    const float* wv  = (const float*)d_in[8];
    const float* bv  = (const float*)d_in[9];
    const float* pw1 = (const float*)d_in[10];
    const float* pb1 = (const float*)d_in[11];
    const float* pg  = (const float*)d_in[12];
    const float* pbt = (const float*)d_in[13];
    const float* pm  = (const float*)d_in[14];
    const float* pv  = (const float*)d_in[15];
    const float* pw2 = (const float*)d_in[16];
    const float* pb2 = (const float*)d_in[17];
    const float* aw1 = (const float*)d_in[18];
    const float* ab1 = (const float*)d_in[19];
    const float* ag  = (const float*)d_in[20];
    const float* abt2= (const float*)d_in[21];
    const float* am  = (const float*)d_in[22];
    const float* av  = (const float*)d_in[23];
    const float* awt = (const float*)d_in[24];
    /* abt (d_in[25]) is constant along the softmax axis -> dropped */
    const float* we  = (const float*)d_in[26];
    const float* be  = (const float*)d_in[27];
    float* out = (float*)d_out;

    setup_kernel<<<64, 256>>>(aw1, awt, we, ag, av, ab1, am, abt2);
    qkv_kernel<<<dim3(256, NB, 3), 256>>>(query, key_feat, wq, bq, wk, bk, wv, bv);
    knn_kernel<<<dim3(32, NB), 128>>>(pos1, pos2);
    prep_kernel<<<PTOT/2, 128>>>(pos1, pos2, pw1, pb1, pg, pbt, pm, pv, pw2, pb2);
    gemm1_kernel<<<MTOT/64, 256>>>();
    gemm2_kernel<<<MTOT/64, 256>>>();
    softmax_kernel<<<PTOT/2, 256>>>();
    final_kernel<<<PTOT*2/16, 256>>>(query, be, out);
}